// round 2
// baseline (speedup 1.0000x reference)
#include <cuda_runtime.h>
#include <math.h>

#define NPIX  (512*1024)
#define NB    8
#define KBINS 16
#define CBINS 4
#define NACC  (KBINS*CBINS + CBINS)   // 64 p_cl + 4 p_l = 68
#define TPB   128
#define GRID  1184                    // 148 SMs * 8

__device__ float g_acc[72];

__global__ void nid_init_kernel() {
    int i = threadIdx.x;
    if (i < 72) g_acc[i] = 0.0f;
}

__global__ void __launch_bounds__(TPB)
nid_main_kernel(const float* __restrict__ cam, const float* __restrict__ lab)
{
    // per-thread 16-bin camera histogram scratch, stride 17 to spread banks
    __shared__ float pc_s[TPB * 17];
    float* __restrict__ myPc = &pc_s[threadIdx.x * 17];

    float acc_cl[KBINS * CBINS];
    float acc_l[CBINS];
#pragma unroll
    for (int i = 0; i < KBINS * CBINS; i++) acc_cl[i] = 0.0f;
#pragma unroll
    for (int c = 0; c < CBINS; c++) acc_l[c] = 0.0f;

    const int stride = GRID * TPB;
#pragma unroll 1
    for (int n = blockIdx.x * TPB + threadIdx.x; n < NPIX; n += stride) {
        float PlS[CBINS];
#pragma unroll
        for (int c = 0; c < CBINS; c++) PlS[c] = 0.0f;
#pragma unroll
        for (int k = 0; k < KBINS; k++) myPc[k] = 0.0f;

#pragma unroll
        for (int b = 0; b < NB; b++) {
            // ---- camera gray ----
            const float* cb = cam + (size_t)b * 3 * NPIX + n;
            float gray = (cb[0] + cb[NPIX] + cb[2 * NPIX]) * (1.0f / 3.0f);

            // ---- label soft-argmax (beta = 500) ----
            const float* lbp = lab + (size_t)b * 4 * NPIX + n;
            float l0 = lbp[0];
            float l1 = lbp[NPIX];
            float l2 = lbp[2 * NPIX];
            float l3 = lbp[3 * NPIX];
            float m  = fmaxf(fmaxf(l0, l1), fmaxf(l2, l3));
            float e0 = __expf((l0 - m) * 500.0f);
            float e1 = __expf((l1 - m) * 500.0f);
            float e2 = __expf((l2 - m) * 500.0f);
            float e3 = __expf((l3 - m) * 500.0f);
            float esum = e0 + e1 + e2 + e3 + 1e-12f;
            float labv = __fdividef(fmaf(3.0f, e3, fmaf(2.0f, e2, e1)), esum);

            // ---- label histogram: exactly one non-saturated edge sigmoid ----
            float u  = labv + 0.5f;
            float ce = rintf(u);                      // nearest edge 0..4
            float x  = (u - ce) * 1000.0f;            // |x| <= 500
            float sg = __fdividef(1.0f, 1.0f + __expf(-x));
            int   ic = (int)ce;
#pragma unroll
            for (int c = 0; c < CBINS; c++) {
                float addv = (ic == c) ? sg : ((ic == c + 1) ? (1.0f - sg) : 0.0f);
                PlS[c] += addv;
            }

            // ---- camera: only edges e0-1..e0+2 are non-saturated ----
            // S(k) = sigmoid(12.5*(g16 - k)); g16 = ie + f
            float g16 = gray * 16.0f;
            float ef  = floorf(g16);
            float f   = g16 - ef;
            int   ie  = (int)ef;
            // e_j = exp(-12.5*(f + 1 - j)) for edges (ie-1+j), j=0..3
            float ex0 = __expf(fmaf(-12.5f, f, -12.5f));  // edge ie-1 (arg<=0 -> S near 1)
            float ex1 = __expf(-12.5f * f);               // edge ie
            float ex2 = __expf(fmaf(-12.5f, f,  12.5f));  // edge ie+1
            float ex3 = __expf(fmaf(-12.5f, f,  25.0f));  // edge ie+2
            float s0 = __fdividef(1.0f, 1.0f + ex0);
            float s1 = __fdividef(1.0f, 1.0f + ex1);
            float s2 = __fdividef(1.0f, 1.0f + ex2);
            float s3 = __fdividef(1.0f, 1.0f + ex3);
            // Pc[ie-2] = 1-s0, Pc[ie-1] = s0-s1, Pc[ie] = s1-s2, Pc[ie+1] = s2-s3
            float w0 = 1.0f - s0;
            float w1 = s0 - s1;
            float w2 = s1 - s2;
            float w3 = s2 - s3;
            int base = ie - 2;
            if ((unsigned)(base + 0) < 16u) myPc[base + 0] += w0;
            if ((unsigned)(base + 1) < 16u) myPc[base + 1] += w1;
            if ((unsigned)(base + 2) < 16u) myPc[base + 2] += w2;
            if ((unsigned)(base + 3) < 16u) myPc[base + 3] += w3;
        }

        // outer-product accumulate: acc_cl[k][c] += Pc[k] * PlS[c]
#pragma unroll
        for (int k = 0; k < KBINS; k++) {
            float pck = myPc[k];
#pragma unroll
            for (int c = 0; c < CBINS; c++)
                acc_cl[k * CBINS + c] = fmaf(pck, PlS[c], acc_cl[k * CBINS + c]);
        }
#pragma unroll
        for (int c = 0; c < CBINS; c++) acc_l[c] += PlS[c];
    }

    // ---- reduction: warp shuffle -> shared -> global atomics ----
    __shared__ float red[TPB / 32][NACC];
    unsigned lane = threadIdx.x & 31u;
    unsigned wrp  = threadIdx.x >> 5;

#pragma unroll
    for (int i = 0; i < KBINS * CBINS; i++) {
        float v = acc_cl[i];
        v += __shfl_down_sync(0xffffffffu, v, 16);
        v += __shfl_down_sync(0xffffffffu, v, 8);
        v += __shfl_down_sync(0xffffffffu, v, 4);
        v += __shfl_down_sync(0xffffffffu, v, 2);
        v += __shfl_down_sync(0xffffffffu, v, 1);
        if (lane == 0) red[wrp][i] = v;
    }
#pragma unroll
    for (int c = 0; c < CBINS; c++) {
        float v = acc_l[c];
        v += __shfl_down_sync(0xffffffffu, v, 16);
        v += __shfl_down_sync(0xffffffffu, v, 8);
        v += __shfl_down_sync(0xffffffffu, v, 4);
        v += __shfl_down_sync(0xffffffffu, v, 2);
        v += __shfl_down_sync(0xffffffffu, v, 1);
        if (lane == 0) red[wrp][KBINS * CBINS + c] = v;
    }
    __syncthreads();
    if (threadIdx.x < NACC) {
        float s = red[0][threadIdx.x] + red[1][threadIdx.x]
                + red[2][threadIdx.x] + red[3][threadIdx.x];
        atomicAdd(&g_acc[threadIdx.x], s);
    }
}

__global__ void nid_final_kernel(float* __restrict__ out)
{
    if (threadIdx.x != 0 || blockIdx.x != 0) return;

    float pcl[KBINS * CBINS];
    float pl[CBINS];
    float scl = 0.0f, sl = 0.0f;
#pragma unroll
    for (int i = 0; i < KBINS * CBINS; i++) { pcl[i] = g_acc[i]; scl += pcl[i]; }
#pragma unroll
    for (int c = 0; c < CBINS; c++) { pl[c] = g_acc[KBINS * CBINS + c]; sl += pl[c]; }

    float inv_scl = 1.0f / scl;
    float inv_sl  = 1.0f / sl;

    float pc[KBINS];
#pragma unroll
    for (int k = 0; k < KBINS; k++) {
        float s = pcl[k * 4 + 0] + pcl[k * 4 + 1] + pcl[k * 4 + 2] + pcl[k * 4 + 3];
        pc[k] = s * inv_scl;   // row-marginal == normalized p_c (label mass == 1/sample)
    }
#pragma unroll
    for (int c = 0; c < CBINS; c++) pl[c] *= inv_sl;

    float I = 0.0f, H = 0.0f;
#pragma unroll
    for (int k = 0; k < KBINS; k++) {
#pragma unroll
        for (int c = 0; c < CBINS; c++) {
            float p  = pcl[k * CBINS + c] * inv_scl;
            float lp = logf(p + 1e-7f);
            float lo = logf(pc[k] * pl[c] + 1e-7f);
            H -= p * lp;
            I += p * (lp - lo);
        }
    }
    float nid = 1.0f - I / H;
    out[0] = (nid - 0.95f) * 20.0f;
}

extern "C" void kernel_launch(void* const* d_in, const int* in_sizes, int n_in,
                              void* d_out, int out_size)
{
    const float* cam = (const float*)d_in[0];   // (8,3,512,1024) fp32
    const float* lab = (const float*)d_in[1];   // (8,4,512,1024) fp32
    float* out = (float*)d_out;

    nid_init_kernel<<<1, 128>>>();
    nid_main_kernel<<<GRID, TPB>>>(cam, lab);
    nid_final_kernel<<<1, 1>>>(out);
}

// round 4
// speedup vs baseline: 1.6138x; 1.6138x over previous
#include <cuda_runtime.h>
#include <math.h>

#define NPIX  (512*1024)
#define NB    8
#define KBINS 16
#define CBINS 4
#define NACC  (KBINS*CBINS + CBINS)   // 64 p_cl + 4 p_l = 68
#define TPB   128
#define GRID  592                     // 148 SMs * 4 blocks (one wave at 128 regs)

__device__ float g_acc[NACC];         // zero at module load; reset by last block each run
__device__ unsigned int g_ticket;     // zero at module load; reset by last block each run

__device__ __forceinline__ float tanh_fast(float x) {
    float r;
    asm("tanh.approx.f32 %0, %1;" : "=f"(r) : "f"(x));
    return r;
}

__global__ void __launch_bounds__(TPB, 4)
nid_kernel(const float* __restrict__ cam, const float* __restrict__ lab,
           float* __restrict__ out)
{
    float acc_cl[KBINS * CBINS];
    float acc_l[CBINS];
#pragma unroll
    for (int i = 0; i < KBINS * CBINS; i++) acc_cl[i] = 0.0f;
#pragma unroll
    for (int c = 0; c < CBINS; c++) acc_l[c] = 0.0f;

    const int stride = GRID * TPB;
#pragma unroll 1
    for (int n = blockIdx.x * TPB + threadIdx.x; n < NPIX; n += stride) {
        // T[k] = sum_b tanh(100*gray_b - 6.25*k)  (edge sigmoids, halved arg;
        // the +1 and *0.5 of sigmoid cancel in differences / normalization)
        float T[KBINS + 1];
        float PlS[CBINS];
#pragma unroll
        for (int k = 0; k <= KBINS; k++) T[k] = 0.0f;
#pragma unroll
        for (int c = 0; c < CBINS; c++) PlS[c] = 0.0f;

#pragma unroll
        for (int b = 0; b < NB; b++) {
            // ---- camera gray ----
            const float* cb = cam + (size_t)b * 3 * NPIX + n;
            float gray = (cb[0] + cb[NPIX] + cb[2 * NPIX]) * (1.0f / 3.0f);

            // ---- label soft-argmax (beta = 500) ----
            const float* lbp = lab + (size_t)b * 4 * NPIX + n;
            float l0 = lbp[0];
            float l1 = lbp[NPIX];
            float l2 = lbp[2 * NPIX];
            float l3 = lbp[3 * NPIX];
            float m  = fmaxf(fmaxf(l0, l1), fmaxf(l2, l3));
            float e0 = __expf((l0 - m) * 500.0f);
            float e1 = __expf((l1 - m) * 500.0f);
            float e2 = __expf((l2 - m) * 500.0f);
            float e3 = __expf((l3 - m) * 500.0f);
            float esum = e0 + e1 + e2 + e3 + 1e-12f;
            float labv = __fdividef(fmaf(3.0f, e3, fmaf(2.0f, e2, e1)), esum);

            // ---- label histogram: single non-saturated edge sigmoid (tanh) ----
            // S(c) = sigmoid((labv - (c-0.5))*1000); only edge nearest labv+0.5 matters.
            float u  = labv + 0.5f;
            float ce = rintf(u);                       // nearest edge 0..4
            float x  = (u - ce) * 500.0f;              // tanh half-argument
            float sg = fmaf(0.5f, tanh_fast(x), 0.5f); // sigmoid value
            int   ic = (int)ce;
#pragma unroll
            for (int c = 0; c < CBINS; c++) {
                float addv = (ic == c) ? sg : ((ic == c + 1) ? (1.0f - sg) : 0.0f);
                PlS[c] += addv;
            }

            // ---- camera: 17 edge tanh values, a = 100*gray ----
            float a = gray * 100.0f;
#pragma unroll
            for (int k = 0; k <= KBINS; k++) {
                T[k] += tanh_fast(a - 6.25f * (float)k);
            }
        }

        // Pc[k] ~ (T[k] - T[k+1])   (x0.5 cancels under normalization)
#pragma unroll
        for (int k = 0; k < KBINS; k++) {
            float pc = T[k] - T[k + 1];
#pragma unroll
            for (int c = 0; c < CBINS; c++)
                acc_cl[k * CBINS + c] = fmaf(pc, PlS[c], acc_cl[k * CBINS + c]);
        }
#pragma unroll
        for (int c = 0; c < CBINS; c++) acc_l[c] += PlS[c];
    }

    // ---- block reduction: warp shuffle -> shared -> global atomics ----
    __shared__ float red[TPB / 32][NACC];
    unsigned lane = threadIdx.x & 31u;
    unsigned wrp  = threadIdx.x >> 5;

#pragma unroll
    for (int i = 0; i < KBINS * CBINS; i++) {
        float v = acc_cl[i];
        v += __shfl_down_sync(0xffffffffu, v, 16);
        v += __shfl_down_sync(0xffffffffu, v, 8);
        v += __shfl_down_sync(0xffffffffu, v, 4);
        v += __shfl_down_sync(0xffffffffu, v, 2);
        v += __shfl_down_sync(0xffffffffu, v, 1);
        if (lane == 0) red[wrp][i] = v;
    }
#pragma unroll
    for (int c = 0; c < CBINS; c++) {
        float v = acc_l[c];
        v += __shfl_down_sync(0xffffffffu, v, 16);
        v += __shfl_down_sync(0xffffffffu, v, 8);
        v += __shfl_down_sync(0xffffffffu, v, 4);
        v += __shfl_down_sync(0xffffffffu, v, 2);
        v += __shfl_down_sync(0xffffffffu, v, 1);
        if (lane == 0) red[wrp][KBINS * CBINS + c] = v;
    }
    __syncthreads();
    if (threadIdx.x < NACC) {
        float s = red[0][threadIdx.x] + red[1][threadIdx.x]
                + red[2][threadIdx.x] + red[3][threadIdx.x];
        atomicAdd(&g_acc[threadIdx.x], s);
    }
    __threadfence();   // publish g_acc contributions before taking a ticket
    __syncthreads();

    // ---- last-block finalize ----
    __shared__ unsigned int s_ticket;
    if (threadIdx.x == 0) s_ticket = atomicAdd(&g_ticket, 1u);
    __syncthreads();
    if (s_ticket != (unsigned)(GRID - 1)) return;

    if (threadIdx.x == 0) {
        __threadfence();  // acquire: see all blocks' atomics

        float pcl[KBINS * CBINS];
        float pl[CBINS];
        float scl = 0.0f, sl = 0.0f;
#pragma unroll
        for (int i = 0; i < KBINS * CBINS; i++) { pcl[i] = g_acc[i]; scl += pcl[i]; }
#pragma unroll
        for (int c = 0; c < CBINS; c++) { pl[c] = g_acc[KBINS * CBINS + c]; sl += pl[c]; }

        float inv_scl = 1.0f / scl;
        float inv_sl  = 1.0f / sl;

        float pc[KBINS];
#pragma unroll
        for (int k = 0; k < KBINS; k++) {
            float s = pcl[k * 4 + 0] + pcl[k * 4 + 1] + pcl[k * 4 + 2] + pcl[k * 4 + 3];
            pc[k] = s * inv_scl;   // row-marginal == normalized p_c (label mass 1/sample)
        }
#pragma unroll
        for (int c = 0; c < CBINS; c++) pl[c] *= inv_sl;

        float I = 0.0f, H = 0.0f;
#pragma unroll
        for (int k = 0; k < KBINS; k++) {
#pragma unroll
            for (int c = 0; c < CBINS; c++) {
                float p  = pcl[k * CBINS + c] * inv_scl;
                float lp = logf(p + 1e-7f);
                float lo = logf(pc[k] * pl[c] + 1e-7f);
                H -= p * lp;
                I += p * (lp - lo);
            }
        }
        float nid = 1.0f - I / H;
        out[0] = (nid - 0.95f) * 20.0f;

        // reset for next graph replay (deterministic across launches)
#pragma unroll
        for (int i = 0; i < NACC; i++) g_acc[i] = 0.0f;
        __threadfence();
        atomicExch(&g_ticket, 0u);
    }
}

extern "C" void kernel_launch(void* const* d_in, const int* in_sizes, int n_in,
                              void* d_out, int out_size)
{
    const float* cam = (const float*)d_in[0];   // (8,3,512,1024) fp32
    const float* lab = (const float*)d_in[1];   // (8,4,512,1024) fp32
    float* out = (float*)d_out;

    nid_kernel<<<GRID, TPB>>>(cam, lab, out);
}